// round 6
// baseline (speedup 1.0000x reference)
#include <cuda_runtime.h>
#include <cuda_fp16.h>
#include <cstdint>

#define DIM 128

// Capacity limits (problem spec: N = 110000 joint rows, E = 1200000 per matrix).
#define NMAX 131072          // max N
#define EMAX 1310720         // max edges per matrix

// Static scratch (no allocations allowed).
__device__ int   g_cnt[2 * NMAX];              // per-(matrix,row) edge counts
__device__ int   g_ofs[2 * NMAX];              // CSR row start (4-edge aligned)
__device__ int   g_cur[2 * NMAX];              // scatter cursors
__device__ int   g_counter;                    // scan block-offset counter
__device__ int2  g_edge[2 * EMAX + 4 * NMAX];  // CSR edges: (col_byte_off, val_bits) + pads
__device__ uint2 g_x1h[NMAX * (DIM / 4)];      // fp16 x1: 32 uint2 per row (256 B/row)

// ---------------------------------------------------------------------------
// K1 (fused): build x1 fp32 into out[0], fp16 copy into g_x1h,
//             histogram edge rows (4 edges per thread via int4).
// ---------------------------------------------------------------------------
__global__ void k_init_hist(const float4* __restrict__ node4,
                            const float4* __restrict__ attri4,
                            float4* __restrict__ out4,
                            const int* __restrict__ r1,
                            const int* __restrict__ r2,
                            long node_f4, long total_f4,
                            int E, int n)
{
    long i = (long)blockIdx.x * blockDim.x + threadIdx.x;

    if (i < total_f4) {
        float4 f = (i < node_f4) ? node4[i] : attri4[i - node_f4];
        out4[i] = f;                                   // fp32 x1 (exact output)
        __half2 h01 = __floats2half2_rn(f.x, f.y);
        __half2 h23 = __floats2half2_rn(f.z, f.w);
        uint2 u;
        u.x = *reinterpret_cast<unsigned*>(&h01);
        u.y = *reinterpret_cast<unsigned*>(&h23);
        g_x1h[i] = u;                                  // fp16 x1 (gather copy)
    }

    int E4 = E >> 2;
    if ((E & 3) == 0) {
        if (i < 2L * E4) {
            int m = (i < E4) ? 0 : 1;
            long e4 = (m == 0) ? i : (i - E4);
            const int4* rp = reinterpret_cast<const int4*>(m == 0 ? r1 : r2);
            int4 r = __ldg(rp + e4);
            int base = m * n;
            atomicAdd(g_cnt + base + r.x, 1);
            atomicAdd(g_cnt + base + r.y, 1);
            atomicAdd(g_cnt + base + r.z, 1);
            atomicAdd(g_cnt + base + r.w, 1);
        }
    } else {
        long twoE = 2L * E;
        if (i < twoE) {
            int b = (i < E) ? __ldg(r1 + i) : (n + __ldg(r2 + (i - E)));
            atomicAdd(g_cnt + b, 1);
        }
    }
}

// ---------------------------------------------------------------------------
// K2: exclusive scan of counts PADDED to multiples of 4 (warp shuffles +
//     atomic block offset). Also writes the val=0 pad edges for each row.
// ---------------------------------------------------------------------------
__global__ void k_scan(int n2)
{
    __shared__ int ws[32];
    __shared__ int base;
    int t = threadIdx.x, lane = t & 31, w = t >> 5;
    int i = blockIdx.x * 1024 + t;
    int v  = (i < n2) ? g_cnt[i] : 0;
    int vp = (v + 3) & ~3;                    // padded count

    int x = vp;
#pragma unroll
    for (int d = 1; d < 32; d <<= 1) {
        int y = __shfl_up_sync(0xffffffffu, x, d);
        if (lane >= d) x += y;
    }
    if (lane == 31) ws[w] = x;
    __syncthreads();
    if (w == 0) {
        int s = ws[lane];
#pragma unroll
        for (int d = 1; d < 32; d <<= 1) {
            int y = __shfl_up_sync(0xffffffffu, s, d);
            if (lane >= d) s += y;
        }
        ws[lane] = s;
    }
    __syncthreads();
    if (t == 0) base = atomicAdd(&g_counter, ws[31]);
    int incl = x + (w > 0 ? ws[w - 1] : 0);
    __syncthreads();
    if (i < n2) {
        int excl = base + incl - vp;          // 4-edge aligned start
        g_ofs[i] = excl;
        g_cur[i] = excl;
        for (int p = v; p < vp; p++)          // zero pad edges (val = 0)
            g_edge[excl + p] = make_int2(0, 0);
    }
}

// ---------------------------------------------------------------------------
// K3: permute edges into CSR order, 4 edges per thread (vector loads).
// Stores (col byte-offset into g_x1h, val_bits).
// ---------------------------------------------------------------------------
__global__ void k_permute(const int* __restrict__ r1, const int* __restrict__ c1,
                          const float* __restrict__ v1,
                          const int* __restrict__ r2, const int* __restrict__ c2,
                          const float* __restrict__ v2,
                          int E, int n)
{
    long i = (long)blockIdx.x * blockDim.x + threadIdx.x;
    int E4 = E >> 2;

    if ((E & 3) == 0) {
        if (i >= 2L * E4) return;
        int m = (i < E4) ? 0 : 1;
        long e4 = (m == 0) ? i : (i - E4);
        const int4*   rp = reinterpret_cast<const int4*>(m == 0 ? r1 : r2);
        const int4*   cp = reinterpret_cast<const int4*>(m == 0 ? c1 : c2);
        const float4* vp = reinterpret_cast<const float4*>(m == 0 ? v1 : v2);
        int4   r = __ldg(rp + e4);
        int4   c = __ldg(cp + e4);
        float4 v = __ldg(vp + e4);
        int base = m * n;
        int p0 = atomicAdd(g_cur + base + r.x, 1);
        int p1 = atomicAdd(g_cur + base + r.y, 1);
        int p2 = atomicAdd(g_cur + base + r.z, 1);
        int p3 = atomicAdd(g_cur + base + r.w, 1);
        g_edge[p0] = make_int2(c.x << 8, __float_as_int(v.x));
        g_edge[p1] = make_int2(c.y << 8, __float_as_int(v.y));
        g_edge[p2] = make_int2(c.z << 8, __float_as_int(v.z));
        g_edge[p3] = make_int2(c.w << 8, __float_as_int(v.w));
    } else {
        long tot = 2L * E;
        if (i >= tot) return;
        int b, col; float val;
        if (i < E) { b = __ldg(r1 + i);     col = __ldg(c1 + i);     val = __ldg(v1 + i); }
        else       { long e = i - E;
                     b = n + __ldg(r2 + e); col = __ldg(c2 + e);     val = __ldg(v2 + e); }
        int pos = atomicAdd(g_cur + b, 1);
        g_edge[pos] = make_int2(col << 8, __float_as_int(val));
    }
}

// ---------------------------------------------------------------------------
// K4: gather SpMM. One warp per row; lane owns 4 of 128 floats.
// Edge meta: broadcast LDG.128 (2 edges per int4). Edge lists padded to
// multiples of 4 with val=0 -> no clamps, no selects, no tail.
// Addressing: edge stores byte offset; lane pointer precomputed.
// ---------------------------------------------------------------------------
__global__ void __launch_bounds__(256)
k_gather(float* __restrict__ out, int n, long total_f)
{
    int gw   = (int)(((long)blockIdx.x * blockDim.x + threadIdx.x) >> 5);
    int lane = threadIdx.x & 31;
    int n2 = 2 * n;
    if (gw >= n2) return;

    int start = __ldg(g_ofs + gw);            // multiple of 4
    int cnt   = __ldg(g_cnt + gw);
    int cp    = (cnt + 3) & ~3;

    const int4* ep4 = reinterpret_cast<const int4*>(g_edge + start);  // 16B aligned
    const char* xb  = reinterpret_cast<const char*>(g_x1h) + lane * 8;

    float a0 = 0.f, a1 = 0.f, a2 = 0.f, a3 = 0.f;

    for (int k = 0; k < cp; k += 4) {
        int4 m0 = __ldg(ep4 + (k >> 1));      // edges k, k+1
        int4 m1 = __ldg(ep4 + (k >> 1) + 1);  // edges k+2, k+3

        uint2 x0 = __ldg(reinterpret_cast<const uint2*>(xb + m0.x));
        uint2 x1 = __ldg(reinterpret_cast<const uint2*>(xb + m0.z));
        uint2 x2 = __ldg(reinterpret_cast<const uint2*>(xb + m1.x));
        uint2 x3 = __ldg(reinterpret_cast<const uint2*>(xb + m1.z));

        float v0 = __int_as_float(m0.y);
        float v1 = __int_as_float(m0.w);
        float v2 = __int_as_float(m1.y);
        float v3 = __int_as_float(m1.w);

        {
            float2 f01 = __half22float2(*reinterpret_cast<__half2*>(&x0.x));
            float2 f23 = __half22float2(*reinterpret_cast<__half2*>(&x0.y));
            a0 = fmaf(v0, f01.x, a0); a1 = fmaf(v0, f01.y, a1);
            a2 = fmaf(v0, f23.x, a2); a3 = fmaf(v0, f23.y, a3);
        }
        {
            float2 f01 = __half22float2(*reinterpret_cast<__half2*>(&x1.x));
            float2 f23 = __half22float2(*reinterpret_cast<__half2*>(&x1.y));
            a0 = fmaf(v1, f01.x, a0); a1 = fmaf(v1, f01.y, a1);
            a2 = fmaf(v1, f23.x, a2); a3 = fmaf(v1, f23.y, a3);
        }
        {
            float2 f01 = __half22float2(*reinterpret_cast<__half2*>(&x2.x));
            float2 f23 = __half22float2(*reinterpret_cast<__half2*>(&x2.y));
            a0 = fmaf(v2, f01.x, a0); a1 = fmaf(v2, f01.y, a1);
            a2 = fmaf(v2, f23.x, a2); a3 = fmaf(v2, f23.y, a3);
        }
        {
            float2 f01 = __half22float2(*reinterpret_cast<__half2*>(&x3.x));
            float2 f23 = __half22float2(*reinterpret_cast<__half2*>(&x3.y));
            a0 = fmaf(v3, f01.x, a0); a1 = fmaf(v3, f01.y, a1);
            a2 = fmaf(v3, f23.x, a2); a3 = fmaf(v3, f23.y, a3);
        }
    }

    long row_off = (gw < n) ? (total_f + (long)gw * DIM)
                            : (2 * total_f + (long)(gw - n) * DIM);
    reinterpret_cast<float4*>(out + row_off)[lane] = make_float4(a0, a1, a2, a3);
}

// ---------------------------------------------------------------------------
extern "C" void kernel_launch(void* const* d_in, const int* in_sizes, int n_in,
                              void* d_out, int out_size)
{
    const float* node  = (const float*)d_in[0];
    const float* attri = (const float*)d_in[1];
    const int*   r1    = (const int*)  d_in[2];
    const int*   c1    = (const int*)  d_in[3];
    const float* v1    = (const float*)d_in[4];
    const int*   r2    = (const int*)  d_in[5];
    const int*   c2    = (const int*)  d_in[6];
    const float* v2    = (const float*)d_in[7];
    float* out = (float*)d_out;

    long node_f  = in_sizes[0];
    long attri_f = in_sizes[1];
    long total_f = node_f + attri_f;
    int  E       = in_sizes[2];
    int  n       = (int)(total_f / DIM);
    int  n2      = 2 * n;

    // K0: zero counters (memset nodes are graph-capturable).
    void *p_cnt = nullptr, *p_counter = nullptr;
    cudaGetSymbolAddress(&p_cnt, g_cnt);
    cudaGetSymbolAddress(&p_counter, g_counter);
    cudaMemsetAsync(p_cnt, 0, (size_t)n2 * sizeof(int));
    cudaMemsetAsync(p_counter, 0, sizeof(int));

    // K1: fused copy + fp16 convert + histogram
    {
        long total4 = total_f / 4;
        long histN  = ((E & 3) == 0) ? (2L * (E >> 2)) : (2L * E);
        long end = total4 > histN ? total4 : histN;
        int  threads = 256;
        long blocks = (end + threads - 1) / threads;
        k_init_hist<<<(unsigned)blocks, threads>>>(
            (const float4*)node, (const float4*)attri, (float4*)out,
            r1, r2, node_f / 4, total4, E, n);
    }

    // K2: scan (+ pad-edge zeroing)
    k_scan<<<(n2 + 1023) / 1024, 1024>>>(n2);

    // K3: permute (4 edges/thread)
    {
        long workers = ((E & 3) == 0) ? (2L * (E >> 2)) : (2L * E);
        int  threads = 256;
        long blocks = (workers + threads - 1) / threads;
        k_permute<<<(unsigned)blocks, threads>>>(r1, c1, v1, r2, c2, v2, E, n);
    }

    // K4: gather SpMM (one warp per row, padded edge lists)
    {
        int threads = 256;
        long blocks = ((long)n2 * 32 + threads - 1) / threads;
        k_gather<<<(unsigned)blocks, threads>>>(out, n, total_f);
    }
}

// round 7
// speedup vs baseline: 1.0118x; 1.0118x over previous
#include <cuda_runtime.h>
#include <cuda_fp16.h>
#include <cstdint>

#define DIM 128

// Capacity limits (problem spec: N = 110000 joint rows, E = 1200000 per matrix).
#define NMAX 131072          // max N
#define EMAX 1310720         // max edges per matrix

// Static scratch (no allocations allowed).
__device__ int   g_cnt[2 * NMAX];              // per-(matrix,row) edge counts
__device__ int   g_cur[2 * NMAX];              // scatter cursors
__device__ int2  g_rowinfo[2 * NMAX];          // (start, cnt) per row, start 2-edge aligned
__device__ int   g_counter;                    // scan block-offset counter
__device__ int2  g_edge[2 * EMAX + 2 * NMAX];  // CSR edges: (col_byte_off, val_half2) + pads
__device__ uint2 g_x1h[NMAX * (DIM / 4)];      // fp16 x1: 32 uint2 per row (256 B/row)

// ---------------------------------------------------------------------------
// K1 (fused): build x1 fp32 into out[0], fp16 copy into g_x1h,
//             histogram edge rows (4 edges per thread via int4).
// ---------------------------------------------------------------------------
__global__ void k_init_hist(const float4* __restrict__ node4,
                            const float4* __restrict__ attri4,
                            float4* __restrict__ out4,
                            const int* __restrict__ r1,
                            const int* __restrict__ r2,
                            long node_f4, long total_f4,
                            int E, int n)
{
    long i = (long)blockIdx.x * blockDim.x + threadIdx.x;

    if (i < total_f4) {
        float4 f = (i < node_f4) ? node4[i] : attri4[i - node_f4];
        out4[i] = f;                                   // fp32 x1 (exact output)
        __half2 h01 = __floats2half2_rn(f.x, f.y);
        __half2 h23 = __floats2half2_rn(f.z, f.w);
        uint2 u;
        u.x = *reinterpret_cast<unsigned*>(&h01);
        u.y = *reinterpret_cast<unsigned*>(&h23);
        g_x1h[i] = u;                                  // fp16 x1 (gather copy)
    }

    int E4 = E >> 2;
    if ((E & 3) == 0) {
        if (i < 2L * E4) {
            int m = (i < E4) ? 0 : 1;
            long e4 = (m == 0) ? i : (i - E4);
            const int4* rp = reinterpret_cast<const int4*>(m == 0 ? r1 : r2);
            int4 r = __ldg(rp + e4);
            int base = m * n;
            atomicAdd(g_cnt + base + r.x, 1);
            atomicAdd(g_cnt + base + r.y, 1);
            atomicAdd(g_cnt + base + r.z, 1);
            atomicAdd(g_cnt + base + r.w, 1);
        }
    } else {
        long twoE = 2L * E;
        if (i < twoE) {
            int b = (i < E) ? __ldg(r1 + i) : (n + __ldg(r2 + (i - E)));
            atomicAdd(g_cnt + b, 1);
        }
    }
}

// ---------------------------------------------------------------------------
// K2: exclusive scan of counts PADDED to multiples of 2 (warp shuffles +
//     atomic block offset). Writes (start,cnt) rowinfo, cursors, and the
//     single val=0 pad edge for odd-count rows.
// ---------------------------------------------------------------------------
__global__ void k_scan(int n2)
{
    __shared__ int ws[32];
    __shared__ int base;
    int t = threadIdx.x, lane = t & 31, w = t >> 5;
    int i = blockIdx.x * 1024 + t;
    int v  = (i < n2) ? g_cnt[i] : 0;
    int vp = (v + 1) & ~1;                    // padded count (multiple of 2)

    int x = vp;
#pragma unroll
    for (int d = 1; d < 32; d <<= 1) {
        int y = __shfl_up_sync(0xffffffffu, x, d);
        if (lane >= d) x += y;
    }
    if (lane == 31) ws[w] = x;
    __syncthreads();
    if (w == 0) {
        int s = ws[lane];
#pragma unroll
        for (int d = 1; d < 32; d <<= 1) {
            int y = __shfl_up_sync(0xffffffffu, s, d);
            if (lane >= d) s += y;
        }
        ws[lane] = s;
    }
    __syncthreads();
    if (t == 0) base = atomicAdd(&g_counter, ws[31]);
    int incl = x + (w > 0 ? ws[w - 1] : 0);
    __syncthreads();
    if (i < n2) {
        int excl = base + incl - vp;          // 2-edge aligned start
        g_rowinfo[i] = make_int2(excl, v);
        g_cur[i] = excl;
        if (v & 1)                            // one zero pad edge
            g_edge[excl + v] = make_int2(0, 0);
    }
}

// ---------------------------------------------------------------------------
// K3: permute edges into CSR order, 4 edges per thread (vector loads).
// Stores (col byte-offset into g_x1h, val duplicated as half2).
// ---------------------------------------------------------------------------
__device__ __forceinline__ int f2h2_bits(float v)
{
    __half2 h = __float2half2_rn(v);
    return *reinterpret_cast<int*>(&h);
}

__global__ void k_permute(const int* __restrict__ r1, const int* __restrict__ c1,
                          const float* __restrict__ v1,
                          const int* __restrict__ r2, const int* __restrict__ c2,
                          const float* __restrict__ v2,
                          int E, int n)
{
    long i = (long)blockIdx.x * blockDim.x + threadIdx.x;
    int E4 = E >> 2;

    if ((E & 3) == 0) {
        if (i >= 2L * E4) return;
        int m = (i < E4) ? 0 : 1;
        long e4 = (m == 0) ? i : (i - E4);
        const int4*   rp = reinterpret_cast<const int4*>(m == 0 ? r1 : r2);
        const int4*   cp = reinterpret_cast<const int4*>(m == 0 ? c1 : c2);
        const float4* vp = reinterpret_cast<const float4*>(m == 0 ? v1 : v2);
        int4   r = __ldg(rp + e4);
        int4   c = __ldg(cp + e4);
        float4 v = __ldg(vp + e4);
        int base = m * n;
        int p0 = atomicAdd(g_cur + base + r.x, 1);
        int p1 = atomicAdd(g_cur + base + r.y, 1);
        int p2 = atomicAdd(g_cur + base + r.z, 1);
        int p3 = atomicAdd(g_cur + base + r.w, 1);
        g_edge[p0] = make_int2(c.x << 8, f2h2_bits(v.x));
        g_edge[p1] = make_int2(c.y << 8, f2h2_bits(v.y));
        g_edge[p2] = make_int2(c.z << 8, f2h2_bits(v.z));
        g_edge[p3] = make_int2(c.w << 8, f2h2_bits(v.w));
    } else {
        long tot = 2L * E;
        if (i >= tot) return;
        int b, col; float val;
        if (i < E) { b = __ldg(r1 + i);     col = __ldg(c1 + i);     val = __ldg(v1 + i); }
        else       { long e = i - E;
                     b = n + __ldg(r2 + e); col = __ldg(c2 + e);     val = __ldg(v2 + e); }
        int pos = atomicAdd(g_cur + b, 1);
        g_edge[pos] = make_int2(col << 8, f2h2_bits(val));
    }
}

// ---------------------------------------------------------------------------
// K4: gather SpMM. One warp per row; lane owns 4 of 128 floats (one uint2 of
// fp16). Edge meta via broadcast LDG.128 (2 edges). fp16 HFMA2 accumulation:
// 2 HFMA2 per edge, zero converts in the loop. Pad edges have val=0.
// ---------------------------------------------------------------------------
__global__ void __launch_bounds__(256)
k_gather(float* __restrict__ out, int n, long total_f)
{
    int gw   = (int)(((long)blockIdx.x * blockDim.x + threadIdx.x) >> 5);
    int lane = threadIdx.x & 31;
    int n2 = 2 * n;
    if (gw >= n2) return;

    int2 ri = __ldg(g_rowinfo + gw);          // (start, cnt)
    int cp  = (ri.y + 1) & ~1;

    const int4* ep4 = reinterpret_cast<const int4*>(g_edge + ri.x);  // 16B aligned
    const char* xb  = reinterpret_cast<const char*>(g_x1h) + lane * 8;

    __half2 h0 = __floats2half2_rn(0.f, 0.f);
    __half2 h1 = h0;

    for (int k = 0; k < cp; k += 2) {
        int4 m = __ldg(ep4++);                // edges k, k+1 (broadcast)
        uint2 x0 = __ldg(reinterpret_cast<const uint2*>(xb + m.x));
        uint2 x1 = __ldg(reinterpret_cast<const uint2*>(xb + m.z));
        __half2 v0 = *reinterpret_cast<__half2*>(&m.y);
        __half2 v1 = *reinterpret_cast<__half2*>(&m.w);
        h0 = __hfma2(v0, *reinterpret_cast<__half2*>(&x0.x), h0);
        h1 = __hfma2(v0, *reinterpret_cast<__half2*>(&x0.y), h1);
        h0 = __hfma2(v1, *reinterpret_cast<__half2*>(&x1.x), h0);
        h1 = __hfma2(v1, *reinterpret_cast<__half2*>(&x1.y), h1);
    }

    float2 f01 = __half22float2(h0);
    float2 f23 = __half22float2(h1);

    long row_off = (gw < n) ? (total_f + (long)gw * DIM)
                            : (2 * total_f + (long)(gw - n) * DIM);
    reinterpret_cast<float4*>(out + row_off)[lane] =
        make_float4(f01.x, f01.y, f23.x, f23.y);
}

// ---------------------------------------------------------------------------
extern "C" void kernel_launch(void* const* d_in, const int* in_sizes, int n_in,
                              void* d_out, int out_size)
{
    const float* node  = (const float*)d_in[0];
    const float* attri = (const float*)d_in[1];
    const int*   r1    = (const int*)  d_in[2];
    const int*   c1    = (const int*)  d_in[3];
    const float* v1    = (const float*)d_in[4];
    const int*   r2    = (const int*)  d_in[5];
    const int*   c2    = (const int*)  d_in[6];
    const float* v2    = (const float*)d_in[7];
    float* out = (float*)d_out;

    long node_f  = in_sizes[0];
    long attri_f = in_sizes[1];
    long total_f = node_f + attri_f;
    int  E       = in_sizes[2];
    int  n       = (int)(total_f / DIM);
    int  n2      = 2 * n;

    // K0: zero counters (memset nodes are graph-capturable).
    void *p_cnt = nullptr, *p_counter = nullptr;
    cudaGetSymbolAddress(&p_cnt, g_cnt);
    cudaGetSymbolAddress(&p_counter, g_counter);
    cudaMemsetAsync(p_cnt, 0, (size_t)n2 * sizeof(int));
    cudaMemsetAsync(p_counter, 0, sizeof(int));

    // K1: fused copy + fp16 convert + histogram
    {
        long total4 = total_f / 4;
        long histN  = ((E & 3) == 0) ? (2L * (E >> 2)) : (2L * E);
        long end = total4 > histN ? total4 : histN;
        int  threads = 256;
        long blocks = (end + threads - 1) / threads;
        k_init_hist<<<(unsigned)blocks, threads>>>(
            (const float4*)node, (const float4*)attri, (float4*)out,
            r1, r2, node_f / 4, total4, E, n);
    }

    // K2: scan (+ pad-edge zeroing, rowinfo)
    k_scan<<<(n2 + 1023) / 1024, 1024>>>(n2);

    // K3: permute (4 edges/thread, half2 vals)
    {
        long workers = ((E & 3) == 0) ? (2L * (E >> 2)) : (2L * E);
        int  threads = 256;
        long blocks = (workers + threads - 1) / threads;
        k_permute<<<(unsigned)blocks, threads>>>(r1, c1, v1, r2, c2, v2, E, n);
    }

    // K4: gather SpMM (one warp per row, HFMA2)
    {
        int threads = 256;
        long blocks = ((long)n2 * 32 + threads - 1) / threads;
        k_gather<<<(unsigned)blocks, threads>>>(out, n, total_f);
    }
}